// round 14
// baseline (speedup 1.0000x reference)
#include <cuda_runtime.h>

#define NB 8       // batch
#define NT 12      // time / feature-in dim
#define NN 20000   // nodes
#define NE 320000  // edges
#define NF 64      // gcn hidden
#define NBT (NB * NT)   // 96 floats per node row
#define CAP 64          // bucket capacity (Poisson(16); P(>64) ~ 1e-20)

// Scratch (__device__ globals; ~25 MB, L2-resident).
// g_cnt starts zeroed (static init) and is re-zeroed by k2 every call.
__device__ __align__(128) float g_xt [(size_t)NN * NBT];  // [n][b*12+t]
__device__ __align__(128) float g_agg[(size_t)NN * NBT];  // [n][b*12+t]
__device__ __align__(128) int2  g_bkt[(size_t)NN * CAP];  // {src*24, w-as-int}
__device__ int g_cnt[NN];

// ---- f32x2 packed helpers ---------------------------------------------------
__device__ __forceinline__ unsigned long long pk2(float lo, float hi) {
    unsigned long long r;
    asm("mov.b64 %0, {%1, %2};" : "=l"(r) : "f"(lo), "f"(hi));
    return r;
}
__device__ __forceinline__ void upk2(float& lo, float& hi, unsigned long long v) {
    asm("mov.b64 {%0, %1}, %2;" : "=f"(lo), "=f"(hi) : "l"(v));
}
#define FFMA2(d, a, b, c) \
    asm("fma.rn.f32x2 %0, %1, %2, %3;" : "=l"(d) : "l"(a), "l"(b), "l"(c))

// ---------------------------------------------------------------------------
// kT: transpose x[B,T,N] -> g_xt[N][B*T], 32-node tiles, float4 both ways.
// ---------------------------------------------------------------------------
__global__ void __launch_bounds__(256) kT(const float* __restrict__ x) {
    __shared__ float s[96 * 33];
    int tid = threadIdx.x;
    int n0 = blockIdx.x * 32;
    const float4* x4 = reinterpret_cast<const float4*>(x);
#pragma unroll
    for (int k = 0; k < 3; ++k) {
        int i = tid + 256 * k;
        int bt = i >> 3, q = i & 7;
        float4 v = x4[(size_t)bt * (NN / 4) + (n0 >> 2) + q];
        s[bt * 33 + 4 * q + 0] = v.x;
        s[bt * 33 + 4 * q + 1] = v.y;
        s[bt * 33 + 4 * q + 2] = v.z;
        s[bt * 33 + 4 * q + 3] = v.w;
    }
    __syncthreads();
    float4* dst = reinterpret_cast<float4*>(g_xt) + (size_t)n0 * 24;
#pragma unroll
    for (int k = 0; k < 3; ++k) {
        int o4 = tid + 256 * k;
        int n = o4 / 24, q = o4 % 24, r = 4 * q;
        dst[o4] = make_float4(s[(r + 0) * 33 + n], s[(r + 1) * 33 + n],
                              s[(r + 2) * 33 + n], s[(r + 3) * 33 + n]);
    }
}

// ---------------------------------------------------------------------------
// kF: bucket edges by destination (slot stores src*24 and weight bits).
// ---------------------------------------------------------------------------
__global__ void __launch_bounds__(256) kF(
        const int* __restrict__ esrc, const int* __restrict__ edst,
        const float* __restrict__ ew) {
    int e = blockIdx.x * 256 + threadIdx.x;   // grid exact: NE/256 blocks
    int d = edst[e];
    int pos = atomicAdd(&g_cnt[d], 1);
    if (pos < CAP)
        g_bkt[(size_t)d * CAP + pos] = make_int2(esrc[e] * 24, __float_as_int(ew[e]));
}

// ---------------------------------------------------------------------------
// k2: gather, one warp per node. Block stages all 8 nodes' bucket slots into
// smem with ONE coalesced 4KB burst (256 int4), then the inner loop reads
// slots via broadcast LDS (no shfl, no per-warp serial L2 dependency).
// 8 LDG.128 in flight per iteration. Resets g_cnt.
// ---------------------------------------------------------------------------
__global__ void __launch_bounds__(256) k2_gather(
        const int* __restrict__ esrc, const int* __restrict__ edst,
        const float* __restrict__ ew) {
    __shared__ int2 s_slot[8][CAP];   // 4 KB
    __shared__ int  s_cnt[8];

    int tid = threadIdx.x;
    int w = tid >> 5, lane = tid & 31;
    int node0 = blockIdx.x * 8;

    // Stage: 8 nodes x 64 slots = 256 int4, one per thread, fully coalesced.
    reinterpret_cast<int4*>(&s_slot[0][0])[tid] =
        reinterpret_cast<const int4*>(g_bkt + (size_t)node0 * CAP)[tid];
    if (tid < 8) {
        int nd = node0 + tid;
        s_cnt[tid] = g_cnt[nd];
        g_cnt[nd] = 0;                // leave zeroed for next call
    }
    __syncthreads();

    int node = node0 + w;
    int cnt = s_cnt[w];

    float4 acc = make_float4(0.f, 0.f, 0.f, 0.f);
    const float4* xt4 = reinterpret_cast<const float4*>(g_xt);

    if (cnt <= CAP) {
        for (int j = 0; j < cnt; j += 8) {
            int   sx[8];
            float wv[8];
#pragma unroll
            for (int k = 0; k < 8; ++k) {
                int idx = j + k;
                int2 sv = (idx < cnt) ? s_slot[w][idx] : make_int2(0, 0);
                sx[k] = sv.x;
                wv[k] = __int_as_float(sv.y);
            }
            if (lane < 24) {
                float4 v[8];
#pragma unroll
                for (int k = 0; k < 8; ++k) v[k] = __ldg(&xt4[(size_t)sx[k] + lane]);
#pragma unroll
                for (int k = 0; k < 8; ++k) {
                    acc.x += wv[k] * v[k].x;
                    acc.y += wv[k] * v[k].y;
                    acc.z += wv[k] * v[k].z;
                    acc.w += wv[k] * v[k].w;
                }
            }
        }
    } else {
        // Unconditional-correctness fallback (statistically unreachable).
        for (int e = 0; e < NE; ++e) {
            if (__ldg(edst + e) == node) {
                float wt = __ldg(ew + e);
                if (lane < 24) {
                    float4 v = __ldg(&xt4[(size_t)__ldg(esrc + e) * 24 + lane]);
                    acc.x += wt * v.x; acc.y += wt * v.y;
                    acc.z += wt * v.z; acc.w += wt * v.w;
                }
            }
        }
    }

    if (lane < 24)
        reinterpret_cast<float4*>(g_agg)[(size_t)node * 24 + lane] = acc;
}

// ---------------------------------------------------------------------------
// k3: epilogue (unchanged). One thread per (node, 4-batch half); weights
// pre-duplicated in smem as float2 {w,w}; LDS.64 + FFMA2 inner loop.
// ---------------------------------------------------------------------------
__global__ void __launch_bounds__(128) k3_out(
        const float* __restrict__ w_gcn, const float* __restrict__ b_gcn,
        const float* __restrict__ w_dense, const float* __restrict__ b_dense,
        float* __restrict__ out) {
    __shared__ float2 s_wg2[NT * NF];   // [t][f] duplicated
    __shared__ float2 s_wd2[NF * NT];   // [f][t] duplicated
    __shared__ float2 s_bg2[NF];
    __shared__ float  s_bd[NT];
    int tid = threadIdx.x;
    for (int i = tid; i < NT * NF; i += 128) {
        float a = w_gcn[i];   s_wg2[i] = make_float2(a, a);
        float b = w_dense[i]; s_wd2[i] = make_float2(b, b);
    }
    if (tid < NF) { float v = b_gcn[tid]; s_bg2[tid] = make_float2(v, v); }
    if (tid < NT) s_bd[tid] = b_dense[tid];
    __syncthreads();

    int gid = blockIdx.x * 128 + tid;     // (n, half): 40000 total
    if (gid >= NN * 2) return;
    int n = gid >> 1, half = gid & 1;     // batches b0 = 4*half .. +3

    unsigned long long A[2][NT], O[2][NT];
    {
        const float4* p = reinterpret_cast<const float4*>(
            g_agg + (size_t)n * NBT + half * 48);
        float a[4][NT];
#pragma unroll
        for (int q = 0; q < 12; ++q) {
            float4 v = p[q];
            int b = q / 3, r = (q % 3) * 4;
            a[b][r + 0] = v.x; a[b][r + 1] = v.y; a[b][r + 2] = v.z; a[b][r + 3] = v.w;
        }
#pragma unroll
        for (int t = 0; t < NT; ++t) {
            A[0][t] = pk2(a[0][t], a[1][t]);
            A[1][t] = pk2(a[2][t], a[3][t]);
            O[0][t] = 0ull;
            O[1][t] = 0ull;
        }
    }

    const unsigned long long* wg2 = reinterpret_cast<const unsigned long long*>(s_wg2);
    const unsigned long long* wd2 = reinterpret_cast<const unsigned long long*>(s_wd2);
    const unsigned long long* bg2 = reinterpret_cast<const unsigned long long*>(s_bg2);

#pragma unroll 4
    for (int f = 0; f < NF; ++f) {
        unsigned long long G0 = bg2[f];
        unsigned long long G1 = G0;
#pragma unroll
        for (int t = 0; t < NT; ++t) {
            unsigned long long w2 = wg2[t * NF + f];
            FFMA2(G0, A[0][t], w2, G0);
            FFMA2(G1, A[1][t], w2, G1);
        }
        float g0l, g0h, g1l, g1h;
        upk2(g0l, g0h, G0); upk2(g1l, g1h, G1);
        G0 = pk2(fmaxf(g0l, 0.f), fmaxf(g0h, 0.f));
        G1 = pk2(fmaxf(g1l, 0.f), fmaxf(g1h, 0.f));
#pragma unroll
        for (int t = 0; t < NT; ++t) {
            unsigned long long w2 = wd2[f * NT + t];
            FFMA2(O[0][t], G0, w2, O[0][t]);
            FFMA2(O[1][t], G1, w2, O[1][t]);
        }
    }

#pragma unroll
    for (int p = 0; p < 2; ++p) {
        float lo[NT], hi[NT];
#pragma unroll
        for (int t = 0; t < NT; ++t) {
            float l, h; upk2(l, h, O[p][t]);
            lo[t] = fmaxf(l + s_bd[t], 0.f);
            hi[t] = fmaxf(h + s_bd[t], 0.f);
        }
        int b_lo = half * 4 + 2 * p;
        float4* q0 = reinterpret_cast<float4*>(out + ((size_t)b_lo * NN + n) * NT);
        float4* q1 = reinterpret_cast<float4*>(out + ((size_t)(b_lo + 1) * NN + n) * NT);
#pragma unroll
        for (int q = 0; q < 3; ++q) {
            q0[q] = make_float4(lo[4*q], lo[4*q+1], lo[4*q+2], lo[4*q+3]);
            q1[q] = make_float4(hi[4*q], hi[4*q+1], hi[4*q+2], hi[4*q+3]);
        }
    }
}

// ---------------------------------------------------------------------------
extern "C" void kernel_launch(void* const* d_in, const int* in_sizes, int n_in,
                              void* d_out, int out_size) {
    const float* x       = (const float*)d_in[0];
    const float* ew      = (const float*)d_in[1];
    const float* w_gcn   = (const float*)d_in[2];
    const float* b_gcn   = (const float*)d_in[3];
    const float* w_dense = (const float*)d_in[4];
    const float* b_dense = (const float*)d_in[5];
    const int*   esrc    = (const int*)d_in[6];
    const int*   edst    = (const int*)d_in[7];
    float* out = (float*)d_out;

    kT<<<NN / 32, 256>>>(x);
    kF<<<NE / 256, 256>>>(esrc, edst, ew);
    k2_gather<<<NN / 8, 256>>>(esrc, edst, ew);
    k3_out<<<(NN * 2 + 127) / 128, 128>>>(w_gcn, b_gcn, w_dense, b_dense, out);
}

// round 15
// speedup vs baseline: 1.0329x; 1.0329x over previous
#include <cuda_runtime.h>

#define NB 8       // batch
#define NT 12      // time / feature-in dim
#define NN 20000   // nodes
#define NE 320000  // edges
#define NF 64      // gcn hidden
#define NBT (NB * NT)   // 96 floats per node row
#define CAP 64          // bucket capacity (Poisson(16); P(>64) ~ 1e-20)

// Scratch (__device__ globals; ~25 MB, L2-resident).
// g_cnt starts zeroed (static init) and is re-zeroed by k2 every call.
__device__ __align__(128) float g_xt [(size_t)NN * NBT];  // [n][b*12+t]
__device__ __align__(128) float g_agg[(size_t)NN * NBT];  // [n][b*12+t]
__device__ __align__(128) int2  g_bkt[(size_t)NN * CAP];  // {src*24, w-as-int}
__device__ int g_cnt[NN];

// ---- f32x2 packed helpers ---------------------------------------------------
__device__ __forceinline__ unsigned long long pk2(float lo, float hi) {
    unsigned long long r;
    asm("mov.b64 %0, {%1, %2};" : "=l"(r) : "f"(lo), "f"(hi));
    return r;
}
__device__ __forceinline__ void upk2(float& lo, float& hi, unsigned long long v) {
    asm("mov.b64 {%0, %1}, %2;" : "=f"(lo), "=f"(hi) : "l"(v));
}
#define FFMA2(d, a, b, c) \
    asm("fma.rn.f32x2 %0, %1, %2, %3;" : "=l"(d) : "l"(a), "l"(b), "l"(c))

// ---------------------------------------------------------------------------
// kT: transpose x[B,T,N] -> g_xt[N][B*T], 32-node tiles, float4 both ways.
// ---------------------------------------------------------------------------
__global__ void __launch_bounds__(256) kT(const float* __restrict__ x) {
    __shared__ float s[96 * 33];
    int tid = threadIdx.x;
    int n0 = blockIdx.x * 32;
    const float4* x4 = reinterpret_cast<const float4*>(x);
#pragma unroll
    for (int k = 0; k < 3; ++k) {
        int i = tid + 256 * k;
        int bt = i >> 3, q = i & 7;
        float4 v = x4[(size_t)bt * (NN / 4) + (n0 >> 2) + q];
        s[bt * 33 + 4 * q + 0] = v.x;
        s[bt * 33 + 4 * q + 1] = v.y;
        s[bt * 33 + 4 * q + 2] = v.z;
        s[bt * 33 + 4 * q + 3] = v.w;
    }
    __syncthreads();
    float4* dst = reinterpret_cast<float4*>(g_xt) + (size_t)n0 * 24;
#pragma unroll
    for (int k = 0; k < 3; ++k) {
        int o4 = tid + 256 * k;
        int n = o4 / 24, q = o4 % 24, r = 4 * q;
        dst[o4] = make_float4(s[(r + 0) * 33 + n], s[(r + 1) * 33 + n],
                              s[(r + 2) * 33 + n], s[(r + 3) * 33 + n]);
    }
}

// ---------------------------------------------------------------------------
// kF: bucket edges by destination (slot stores src*24 and weight bits).
// ---------------------------------------------------------------------------
__global__ void __launch_bounds__(256) kF(
        const int* __restrict__ esrc, const int* __restrict__ edst,
        const float* __restrict__ ew) {
    int e = blockIdx.x * 256 + threadIdx.x;   // grid exact: NE/256 blocks
    int d = edst[e];
    int pos = atomicAdd(&g_cnt[d], 1);
    if (pos < CAP)
        g_bkt[(size_t)d * CAP + pos] = make_int2(esrc[e] * 24, __float_as_int(ew[e]));
}

// ---------------------------------------------------------------------------
// k2: gather, one warp per node. Block stages all 8 nodes' bucket slots into
// smem with ONE coalesced 4KB burst (256 int4), then the inner loop reads
// slots via broadcast LDS (no shfl, no per-warp serial L2 dependency).
// 8 LDG.128 in flight per iteration. Resets g_cnt.
// ---------------------------------------------------------------------------
__global__ void __launch_bounds__(256) k2_gather(
        const int* __restrict__ esrc, const int* __restrict__ edst,
        const float* __restrict__ ew) {
    __shared__ int2 s_slot[8][CAP];   // 4 KB
    __shared__ int  s_cnt[8];

    int tid = threadIdx.x;
    int w = tid >> 5, lane = tid & 31;
    int node0 = blockIdx.x * 8;

    // Stage: 8 nodes x 64 slots = 256 int4, one per thread, fully coalesced.
    reinterpret_cast<int4*>(&s_slot[0][0])[tid] =
        reinterpret_cast<const int4*>(g_bkt + (size_t)node0 * CAP)[tid];
    if (tid < 8) {
        int nd = node0 + tid;
        s_cnt[tid] = g_cnt[nd];
        g_cnt[nd] = 0;                // leave zeroed for next call
    }
    __syncthreads();

    int node = node0 + w;
    int cnt = s_cnt[w];

    float4 acc = make_float4(0.f, 0.f, 0.f, 0.f);
    const float4* xt4 = reinterpret_cast<const float4*>(g_xt);

    if (cnt <= CAP) {
        for (int j = 0; j < cnt; j += 8) {
            int   sx[8];
            float wv[8];
#pragma unroll
            for (int k = 0; k < 8; ++k) {
                int idx = j + k;
                int2 sv = (idx < cnt) ? s_slot[w][idx] : make_int2(0, 0);
                sx[k] = sv.x;
                wv[k] = __int_as_float(sv.y);
            }
            if (lane < 24) {
                float4 v[8];
#pragma unroll
                for (int k = 0; k < 8; ++k) v[k] = __ldg(&xt4[(size_t)sx[k] + lane]);
#pragma unroll
                for (int k = 0; k < 8; ++k) {
                    acc.x += wv[k] * v[k].x;
                    acc.y += wv[k] * v[k].y;
                    acc.z += wv[k] * v[k].z;
                    acc.w += wv[k] * v[k].w;
                }
            }
        }
    } else {
        // Unconditional-correctness fallback (statistically unreachable).
        for (int e = 0; e < NE; ++e) {
            if (__ldg(edst + e) == node) {
                float wt = __ldg(ew + e);
                if (lane < 24) {
                    float4 v = __ldg(&xt4[(size_t)__ldg(esrc + e) * 24 + lane]);
                    acc.x += wt * v.x; acc.y += wt * v.y;
                    acc.z += wt * v.z; acc.w += wt * v.w;
                }
            }
        }
    }

    if (lane < 24)
        reinterpret_cast<float4*>(g_agg)[(size_t)node * 24 + lane] = acc;
}

// ---------------------------------------------------------------------------
// k3: epilogue (unchanged). One thread per (node, 4-batch half); weights
// pre-duplicated in smem as float2 {w,w}; LDS.64 + FFMA2 inner loop.
// ---------------------------------------------------------------------------
__global__ void __launch_bounds__(128) k3_out(
        const float* __restrict__ w_gcn, const float* __restrict__ b_gcn,
        const float* __restrict__ w_dense, const float* __restrict__ b_dense,
        float* __restrict__ out) {
    __shared__ float2 s_wg2[NT * NF];   // [t][f] duplicated
    __shared__ float2 s_wd2[NF * NT];   // [f][t] duplicated
    __shared__ float2 s_bg2[NF];
    __shared__ float  s_bd[NT];
    int tid = threadIdx.x;
    for (int i = tid; i < NT * NF; i += 128) {
        float a = w_gcn[i];   s_wg2[i] = make_float2(a, a);
        float b = w_dense[i]; s_wd2[i] = make_float2(b, b);
    }
    if (tid < NF) { float v = b_gcn[tid]; s_bg2[tid] = make_float2(v, v); }
    if (tid < NT) s_bd[tid] = b_dense[tid];
    __syncthreads();

    int gid = blockIdx.x * 128 + tid;     // (n, half): 40000 total
    if (gid >= NN * 2) return;
    int n = gid >> 1, half = gid & 1;     // batches b0 = 4*half .. +3

    unsigned long long A[2][NT], O[2][NT];
    {
        const float4* p = reinterpret_cast<const float4*>(
            g_agg + (size_t)n * NBT + half * 48);
        float a[4][NT];
#pragma unroll
        for (int q = 0; q < 12; ++q) {
            float4 v = p[q];
            int b = q / 3, r = (q % 3) * 4;
            a[b][r + 0] = v.x; a[b][r + 1] = v.y; a[b][r + 2] = v.z; a[b][r + 3] = v.w;
        }
#pragma unroll
        for (int t = 0; t < NT; ++t) {
            A[0][t] = pk2(a[0][t], a[1][t]);
            A[1][t] = pk2(a[2][t], a[3][t]);
            O[0][t] = 0ull;
            O[1][t] = 0ull;
        }
    }

    const unsigned long long* wg2 = reinterpret_cast<const unsigned long long*>(s_wg2);
    const unsigned long long* wd2 = reinterpret_cast<const unsigned long long*>(s_wd2);
    const unsigned long long* bg2 = reinterpret_cast<const unsigned long long*>(s_bg2);

#pragma unroll 4
    for (int f = 0; f < NF; ++f) {
        unsigned long long G0 = bg2[f];
        unsigned long long G1 = G0;
#pragma unroll
        for (int t = 0; t < NT; ++t) {
            unsigned long long w2 = wg2[t * NF + f];
            FFMA2(G0, A[0][t], w2, G0);
            FFMA2(G1, A[1][t], w2, G1);
        }
        float g0l, g0h, g1l, g1h;
        upk2(g0l, g0h, G0); upk2(g1l, g1h, G1);
        G0 = pk2(fmaxf(g0l, 0.f), fmaxf(g0h, 0.f));
        G1 = pk2(fmaxf(g1l, 0.f), fmaxf(g1h, 0.f));
#pragma unroll
        for (int t = 0; t < NT; ++t) {
            unsigned long long w2 = wd2[f * NT + t];
            FFMA2(O[0][t], G0, w2, O[0][t]);
            FFMA2(O[1][t], G1, w2, O[1][t]);
        }
    }

#pragma unroll
    for (int p = 0; p < 2; ++p) {
        float lo[NT], hi[NT];
#pragma unroll
        for (int t = 0; t < NT; ++t) {
            float l, h; upk2(l, h, O[p][t]);
            lo[t] = fmaxf(l + s_bd[t], 0.f);
            hi[t] = fmaxf(h + s_bd[t], 0.f);
        }
        int b_lo = half * 4 + 2 * p;
        float4* q0 = reinterpret_cast<float4*>(out + ((size_t)b_lo * NN + n) * NT);
        float4* q1 = reinterpret_cast<float4*>(out + ((size_t)(b_lo + 1) * NN + n) * NT);
#pragma unroll
        for (int q = 0; q < 3; ++q) {
            q0[q] = make_float4(lo[4*q], lo[4*q+1], lo[4*q+2], lo[4*q+3]);
            q1[q] = make_float4(hi[4*q], hi[4*q+1], hi[4*q+2], hi[4*q+3]);
        }
    }
}

// ---------------------------------------------------------------------------
extern "C" void kernel_launch(void* const* d_in, const int* in_sizes, int n_in,
                              void* d_out, int out_size) {
    const float* x       = (const float*)d_in[0];
    const float* ew      = (const float*)d_in[1];
    const float* w_gcn   = (const float*)d_in[2];
    const float* b_gcn   = (const float*)d_in[3];
    const float* w_dense = (const float*)d_in[4];
    const float* b_dense = (const float*)d_in[5];
    const int*   esrc    = (const int*)d_in[6];
    const int*   edst    = (const int*)d_in[7];
    float* out = (float*)d_out;

    kT<<<NN / 32, 256>>>(x);
    kF<<<NE / 256, 256>>>(esrc, edst, ew);
    k2_gather<<<NN / 8, 256>>>(esrc, edst, ew);
    k3_out<<<(NN * 2 + 127) / 128, 128>>>(w_gcn, b_gcn, w_dense, b_dense, out);
}